// round 11
// baseline (speedup 1.0000x reference)
#include <cuda_runtime.h>
#include <stdint.h>

#define Bc    64
#define CIN   256
#define COUT  256
#define HW    28
#define NPIX  (HW*HW)            // 784
#define NW    (COUT*CIN*9)       // 589824
#define KK    8
#define PDIM  30
#define PPIX  (PDIM*PDIM)        // 900

// ---------------- device scratch ----------------
__device__ __align__(16) uint32_t g_w[COUT * 9 * 8];          // [o][t][cw] sign bits
__device__ int                    g_corr[COUT * 9];           // 256 - 2*popc(w[o][t])
__device__ __align__(16) uint32_t g_pabits[(size_t)Bc * PPIX * 8]; // padded bit image

// ---------------------------------------------------------------------------
// Kernel 1: fused prep. Blocks [0,256): weights; [256,481): activations.
// grid <<<481, 256>>>
// ---------------------------------------------------------------------------
__global__ void prep_kernel(const float* __restrict__ M, const float* __restrict__ Z,
                            const float* __restrict__ rv, const float* __restrict__ x)
{
    __shared__ float swv[2304];
    __shared__ int   sP[9];

    if (blockIdx.x < COUT) {
        const int o    = blockIdx.x;
        const int c    = threadIdx.x;
        const int lane = c & 31;
        const int cw   = c >> 5;

        if (c < 9) sP[c] = 0;

        float rvl[KK];
#pragma unroll
        for (int k = 0; k < KK; k++) rvl[k] = __ldg(rv + k);

        float wv9[9];
        {
            const float* Mp = M + (size_t)o * 2304;
#pragma unroll
            for (int i = 0; i < 9; i++) wv9[i] = Mp[i * 256 + c];
#pragma unroll
            for (int k = 0; k < KK; k++) {
                const float* zp = Z + (size_t)k * NW + (size_t)o * 2304;
#pragma unroll
                for (int i = 0; i < 9; i++) wv9[i] += rvl[k] * zp[i * 256 + c];
            }
        }
#pragma unroll
        for (int i = 0; i < 9; i++) swv[i * 256 + c] = wv9[i];
        __syncthreads();

#pragma unroll
        for (int j = 0; j < 9; j++) {
            unsigned bit  = __float_as_uint(swv[c * 9 + j]) >> 31;
            unsigned mask = __ballot_sync(0xffffffffu, bit);
            if (lane == 0) {
                g_w[(o * 9 + j) * 8 + cw] = mask;
                atomicAdd(&sP[j], __popc(mask));
            }
        }
        __syncthreads();
        if (c < 9) g_corr[o * 9 + c] = 256 - 2 * sP[c];
        return;
    }

    const int gid = (blockIdx.x - COUT) * 256 + threadIdx.x;
    if (gid >= Bc * PPIX) return;
    const int b  = gid / PPIX;
    const int pp = gid - b * PPIX;
    const int py = pp / PDIM;
    const int px = pp - py * PDIM;

    uint4* dst = (uint4*)(g_pabits + ((size_t)b * PPIX + pp) * 8);

    if (py == 0 || py == PDIM - 1 || px == 0 || px == PDIM - 1) {
        uint4 z = make_uint4(0, 0, 0, 0);
        dst[0] = z; dst[1] = z;
        return;
    }
    const float* xp = x + (size_t)b * CIN * NPIX + (py - 1) * HW + (px - 1);
    uint32_t w[8];
#pragma unroll
    for (int cw = 0; cw < 8; cw++) {
        uint32_t m = 0;
#pragma unroll
        for (int j = 0; j < 32; j++) {
            uint32_t s = __float_as_uint(xp[(size_t)(cw * 32 + j) * NPIX]) >> 31;
            m |= s << j;
        }
        w[cw] = m;
    }
    dst[0] = make_uint4(w[0], w[1], w[2], w[3]);
    dst[1] = make_uint4(w[4], w[5], w[6], w[7]);
}

// ---------------------------------------------------------------------------
// Kernel 2: XNOR-popcount conv, 7-row bands, row-structured inner loop.
// __launch_bounds__(256,2) + anti-hoist barriers -> regs <=128 -> 2 CTA/SM.
// grid <<<256, 256, 38336>>>
// ---------------------------------------------------------------------------
#define SM_ABITS 0                      // 9 rows x 30 px x 32B = 8640
#define SM_STAGE 8640                   // 8 warps x 32 x 29 floats = 29696
#define SM_TOTAL (8640 + 29696)

#define P8(A0, A1, W0, W1) \
    (__popc((A0).x ^ (W0).x) + __popc((A0).y ^ (W0).y) + \
     __popc((A0).z ^ (W0).z) + __popc((A0).w ^ (W0).w) + \
     __popc((A1).x ^ (W1).x) + __popc((A1).y ^ (W1).y) + \
     __popc((A1).z ^ (W1).z) + __popc((A1).w ^ (W1).w))

__global__ void __launch_bounds__(256, 2)
conv_pop_kernel(const float* __restrict__ alpha, float* __restrict__ out)
{
    extern __shared__ __align__(16) uint8_t smem[];

    const int tid  = threadIdx.x;
    const int wid  = tid >> 5;
    const int lane = tid & 31;

    const int b    = blockIdx.x >> 2;
    const int band = blockIdx.x & 3;
    const int r0   = band * 7;

    // cooperative load: padded rows r0..r0+8 (540 uint4, contiguous)
    {
        const uint4* src = (const uint4*)(g_pabits + ((size_t)b * PPIX + r0 * PDIM) * 8);
        uint4* d4 = (uint4*)(smem + SM_ABITS);
        for (int i = tid; i < 9 * PDIM * 2; i += 256) d4[i] = src[i];
    }

    const int o = wid * 32 + lane;
    int corr[9];
#pragma unroll
    for (int t = 0; t < 9; t++) corr[t] = __ldg(g_corr + o * 9 + t);
    const float av = __ldg(alpha + o);
    const uint4* wbase = (const uint4*)(g_w + o * 72);

    __syncthreads();

    const uint32_t* ab = (const uint32_t*)(smem + SM_ABITS);
    float* stage = (float*)(smem + SM_STAGE) + wid * (32 * 29);

#pragma unroll 1
    for (int ry = 0; ry < 7; ry++) {
        const int y = r0 + ry;

        int acc[28];
#pragma unroll
        for (int xx = 0; xx < 28; xx++) acc[xx] = 0;

#pragma unroll 1
        for (int kh = 0; kh < 3; kh++) {
            const uint4* wp = wbase + kh * 6;
            const uint4 w00 = __ldg(wp + 0), w01 = __ldg(wp + 1);   // kw=0
            const uint4 w10 = __ldg(wp + 2), w11 = __ldg(wp + 3);   // kw=1
            const uint4 w20 = __ldg(wp + 4), w21 = __ldg(wp + 5);   // kw=2
            const uint4* rowp = (const uint4*)(ab + (ry + kh) * PDIM * 8);

            // 6 chunks of 5 pixels; barrier after each chunk prevents ptxas
            // from hoisting all 30 pixel loads (kept regs at 255 in R10).
#pragma unroll
            for (int chunk = 0; chunk < 6; chunk++) {
#pragma unroll
                for (int i = 0; i < 5; i++) {
                    const int px = chunk * 5 + i;
                    const uint4 a0 = rowp[px * 2];
                    const uint4 a1 = rowp[px * 2 + 1];
                    if (px < 28)             acc[px]     += P8(a0, a1, w00, w01);
                    if (px >= 1 && px <= 28) acc[px - 1] += P8(a0, a1, w10, w11);
                    if (px >= 2)             acc[px - 2] += P8(a0, a1, w20, w21);
                }
                asm volatile("" ::: "memory");
            }
        }

        // pad corrections (row-uniform + column edges)
        const int rowc = (y == 0)  ? (corr[0] + corr[1] + corr[2])
                       : (y == 27) ? (corr[6] + corr[7] + corr[8]) : 0;
        int c0  = corr[0] + corr[3] + corr[6];
        int c27 = corr[2] + corr[5] + corr[8];
        if (y == 0)  { c0 -= corr[0]; c27 -= corr[2]; }
        if (y == 27) { c0 -= corr[6]; c27 -= corr[8]; }

#pragma unroll
        for (int xx = 0; xx < 28; xx++) {
            int cs = rowc;
            if (xx == 0)  cs += c0;
            if (xx == 27) cs += c27;
            stage[lane * 29 + xx] = av * (float)(2304 - 2 * acc[xx] - cs);
        }

        __syncwarp();
        float* outb = out + ((size_t)(b * COUT + wid * 32) * HW + y) * HW;
        if (lane < HW) {
#pragma unroll 4
            for (int oo = 0; oo < 32; oo++)
                outb[(size_t)oo * NPIX + lane] = stage[oo * 29 + lane];
        }
        __syncwarp();
    }
}

// ---------------------------------------------------------------------------
extern "C" void kernel_launch(void* const* d_in, const int* in_sizes, int n_in,
                              void* d_out, int out_size)
{
    const float* x  = (const float*)d_in[0];
    const float* M  = (const float*)d_in[1];
    const float* Z  = (const float*)d_in[2];
    const float* al = (const float*)d_in[3];
    const float* rv = (const float*)d_in[4];

    cudaFuncSetAttribute(conv_pop_kernel,
                         cudaFuncAttributeMaxDynamicSharedMemorySize, SM_TOTAL);

    prep_kernel<<<COUT + (Bc * PPIX + 255) / 256, 256>>>(M, Z, rv, x);
    conv_pop_kernel<<<Bc * 4, 256, SM_TOTAL>>>(al, (float*)d_out);
}

// round 12
// speedup vs baseline: 1.2640x; 1.2640x over previous
#include <cuda_runtime.h>
#include <stdint.h>

#define Bc    64
#define CIN   256
#define COUT  256
#define HW    28
#define NPIX  (HW*HW)            // 784
#define NW    (COUT*CIN*9)       // 589824
#define KK    8
#define PDIM  30
#define PPIX  (PDIM*PDIM)        // 900

// ---------------- device scratch ----------------
__device__ __align__(16) uint32_t g_w[COUT * 9 * 8];          // [o][t][cw] sign bits
__device__ int                    g_corr[COUT * 9];           // 256 - 2*popc(w[o][t])
__device__ __align__(16) uint32_t g_pabits[(size_t)Bc * PPIX * 8]; // padded bit image

// ---------------------------------------------------------------------------
// Kernel 1: fused prep. Blocks [0,256): weights; [256,481): activations.
// grid <<<481, 256>>>
// ---------------------------------------------------------------------------
__global__ void prep_kernel(const float* __restrict__ M, const float* __restrict__ Z,
                            const float* __restrict__ rv, const float* __restrict__ x)
{
    __shared__ float swv[2304];
    __shared__ int   sP[9];

    if (blockIdx.x < COUT) {
        const int o    = blockIdx.x;
        const int c    = threadIdx.x;
        const int lane = c & 31;
        const int cw   = c >> 5;

        if (c < 9) sP[c] = 0;

        float rvl[KK];
#pragma unroll
        for (int k = 0; k < KK; k++) rvl[k] = __ldg(rv + k);

        float wv9[9];
        {
            const float* Mp = M + (size_t)o * 2304;
#pragma unroll
            for (int i = 0; i < 9; i++) wv9[i] = Mp[i * 256 + c];
#pragma unroll
            for (int k = 0; k < KK; k++) {
                const float* zp = Z + (size_t)k * NW + (size_t)o * 2304;
#pragma unroll
                for (int i = 0; i < 9; i++) wv9[i] += rvl[k] * zp[i * 256 + c];
            }
        }
#pragma unroll
        for (int i = 0; i < 9; i++) swv[i * 256 + c] = wv9[i];
        __syncthreads();

#pragma unroll
        for (int j = 0; j < 9; j++) {
            unsigned bit  = __float_as_uint(swv[c * 9 + j]) >> 31;
            unsigned mask = __ballot_sync(0xffffffffu, bit);
            if (lane == 0) {
                g_w[(o * 9 + j) * 8 + cw] = mask;
                atomicAdd(&sP[j], __popc(mask));
            }
        }
        __syncthreads();
        if (c < 9) g_corr[o * 9 + c] = 256 - 2 * sP[c];
        return;
    }

    const int gid = (blockIdx.x - COUT) * 256 + threadIdx.x;
    if (gid >= Bc * PPIX) return;
    const int b  = gid / PPIX;
    const int pp = gid - b * PPIX;
    const int py = pp / PDIM;
    const int px = pp - py * PDIM;

    uint4* dst = (uint4*)(g_pabits + ((size_t)b * PPIX + pp) * 8);

    if (py == 0 || py == PDIM - 1 || px == 0 || px == PDIM - 1) {
        uint4 z = make_uint4(0, 0, 0, 0);
        dst[0] = z; dst[1] = z;
        return;
    }
    const float* xp = x + (size_t)b * CIN * NPIX + (py - 1) * HW + (px - 1);
    uint32_t w[8];
#pragma unroll
    for (int cw = 0; cw < 8; cw++) {
        uint32_t m = 0;
#pragma unroll
        for (int j = 0; j < 32; j++) {
            uint32_t s = __float_as_uint(xp[(size_t)(cw * 32 + j) * NPIX]) >> 31;
            m |= s << j;
        }
        w[cw] = m;
    }
    dst[0] = make_uint4(w[0], w[1], w[2], w[3]);
    dst[1] = make_uint4(w[4], w[5], w[6], w[7]);
}

// ---------------------------------------------------------------------------
// Kernel 2: XNOR-popcount conv, 4-row bands, half-row split across 16 warps.
// Warps 0-7: x in [0,14); warps 8-15: x in [14,28). acc[14]/thread -> ~110 regs.
// grid <<<448, 512, 35456>>>
// ---------------------------------------------------------------------------
#define SM_ABITS 0                      // 6 rows x 30 px x 32B = 5760
#define SM_STAGE 5760                   // 8 outch-groups x 32 x 29 floats = 29696
#define SM_TOTAL (5760 + 29696)

#define P8(A0, A1, W0, W1) \
    (__popc((A0).x ^ (W0).x) + __popc((A0).y ^ (W0).y) + \
     __popc((A0).z ^ (W0).z) + __popc((A0).w ^ (W0).w) + \
     __popc((A1).x ^ (W1).x) + __popc((A1).y ^ (W1).y) + \
     __popc((A1).z ^ (W1).z) + __popc((A1).w ^ (W1).w))

__global__ void __launch_bounds__(512, 1)
conv_pop_kernel(const float* __restrict__ alpha, float* __restrict__ out)
{
    extern __shared__ __align__(16) uint8_t smem[];

    const int tid  = threadIdx.x;
    const int wid  = tid >> 5;
    const int lane = tid & 31;
    const int og   = wid & 7;           // outch group
    const int half = wid >> 3;          // 0: x 0..13, 1: x 14..27
    const int xs   = half * 14;

    const int b    = blockIdx.x / 7;
    const int band = blockIdx.x - b * 7;
    const int r0   = band * 4;

    // cooperative load: padded rows r0..r0+5 (360 uint4, contiguous)
    {
        const uint4* src = (const uint4*)(g_pabits + ((size_t)b * PPIX + r0 * PDIM) * 8);
        uint4* d4 = (uint4*)(smem + SM_ABITS);
        if (tid < 360) d4[tid] = src[tid];
    }

    const int o = og * 32 + lane;
    int corr[9];
#pragma unroll
    for (int t = 0; t < 9; t++) corr[t] = __ldg(g_corr + o * 9 + t);
    const float av = __ldg(alpha + o);
    const uint4* wbase = (const uint4*)(g_w + o * 72);

    __syncthreads();

    const uint32_t* ab = (const uint32_t*)(smem + SM_ABITS);
    float* stage = (float*)(smem + SM_STAGE) + og * (32 * 29);

#pragma unroll 1
    for (int ry = 0; ry < 4; ry++) {
        const int y = r0 + ry;

        int acc[14];
#pragma unroll
        for (int i = 0; i < 14; i++) acc[i] = 0;

#pragma unroll 1
        for (int kh = 0; kh < 3; kh++) {
            const uint4* wp = wbase + kh * 6;
            const uint4 w00 = __ldg(wp + 0), w01 = __ldg(wp + 1);   // kw=0
            const uint4 w10 = __ldg(wp + 2), w11 = __ldg(wp + 3);   // kw=1
            const uint4 w20 = __ldg(wp + 4), w21 = __ldg(wp + 5);   // kw=2
            const uint4* rowp = (const uint4*)(ab + (ry + kh) * PDIM * 8) + xs * 2;
#pragma unroll
            for (int j = 0; j < 16; j++) {          // padded px = xs + j
                const uint4 a0 = rowp[j * 2];
                const uint4 a1 = rowp[j * 2 + 1];
                if (j < 14)             acc[j]     += P8(a0, a1, w00, w01);
                if (j >= 1 && j <= 14)  acc[j - 1] += P8(a0, a1, w10, w11);
                if (j >= 2)             acc[j - 2] += P8(a0, a1, w20, w21);
            }
        }

        // pad corrections (row-uniform + column edges)
        const int rowc = (y == 0)  ? (corr[0] + corr[1] + corr[2])
                       : (y == 27) ? (corr[6] + corr[7] + corr[8]) : 0;
        int cedge = (half == 0) ? (corr[0] + corr[3] + corr[6])
                                : (corr[2] + corr[5] + corr[8]);
        if (y == 0)  cedge -= (half == 0) ? corr[0] : corr[2];
        if (y == 27) cedge -= (half == 0) ? corr[6] : corr[8];

#pragma unroll
        for (int i = 0; i < 14; i++) {
            int cs = rowc;
            if (half == 0 && i == 0)  cs += cedge;
            if (half == 1 && i == 13) cs += cedge;
            stage[lane * 29 + xs + i] = av * (float)(2304 - 2 * acc[i] - cs);
        }

        __syncthreads();
        // coalesced writeback by half-1 warps: lanes sweep x, loop over 32 outch
        if (half == 1 && lane < HW) {
            float* outb = out + ((size_t)(b * COUT + og * 32) * HW + y) * HW;
#pragma unroll 4
            for (int oo = 0; oo < 32; oo++)
                outb[(size_t)oo * NPIX + lane] = stage[oo * 29 + lane];
        }
        __syncthreads();
    }
}

// ---------------------------------------------------------------------------
extern "C" void kernel_launch(void* const* d_in, const int* in_sizes, int n_in,
                              void* d_out, int out_size)
{
    const float* x  = (const float*)d_in[0];
    const float* M  = (const float*)d_in[1];
    const float* Z  = (const float*)d_in[2];
    const float* al = (const float*)d_in[3];
    const float* rv = (const float*)d_in[4];

    cudaFuncSetAttribute(conv_pop_kernel,
                         cudaFuncAttributeMaxDynamicSharedMemorySize, SM_TOTAL);

    prep_kernel<<<COUT + (Bc * PPIX + 255) / 256, 256>>>(M, Z, rv, x);
    conv_pop_kernel<<<Bc * 7, 512, SM_TOTAL>>>(al, (float*)d_out);
}

// round 13
// speedup vs baseline: 1.7019x; 1.3465x over previous
#include <cuda_runtime.h>
#include <stdint.h>

#define Bc    64
#define CIN   256
#define COUT  256
#define HW    28
#define NPIX  (HW*HW)            // 784
#define NW    (COUT*CIN*9)       // 589824
#define KK    8
#define PDIM  30
#define PPIX  (PDIM*PDIM)        // 900

// ---------------- device scratch ----------------
__device__ __align__(16) uint32_t g_w[COUT * 9 * 8];          // [o][t][cw] sign bits
__device__ int                    g_corr[COUT * 9];           // 256 - 2*popc(w[o][t])
__device__ __align__(16) uint32_t g_pabits[(size_t)Bc * PPIX * 8]; // padded bit image

__device__ __forceinline__ uint32_t xor3(uint32_t a, uint32_t b, uint32_t c) {
    uint32_t r;
    asm("lop3.b32 %0, %1, %2, %3, 0x96;" : "=r"(r) : "r"(a), "r"(b), "r"(c));
    return r;
}
__device__ __forceinline__ uint32_t maj3(uint32_t a, uint32_t b, uint32_t c) {
    uint32_t r;
    asm("lop3.b32 %0, %1, %2, %3, 0xE8;" : "=r"(r) : "r"(a), "r"(b), "r"(c));
    return r;
}

// ---------------------------------------------------------------------------
// Kernel 1: fused prep. Blocks [0,256): weights; [256,481): activations.
// grid <<<481, 256>>>
// ---------------------------------------------------------------------------
__global__ void prep_kernel(const float* __restrict__ M, const float* __restrict__ Z,
                            const float* __restrict__ rv, const float* __restrict__ x)
{
    __shared__ float swv[2304];
    __shared__ int   sP[9];

    if (blockIdx.x < COUT) {
        const int o    = blockIdx.x;
        const int c    = threadIdx.x;
        const int lane = c & 31;
        const int cw   = c >> 5;

        if (c < 9) sP[c] = 0;

        float rvl[KK];
#pragma unroll
        for (int k = 0; k < KK; k++) rvl[k] = __ldg(rv + k);

        float wv9[9];
        {
            const float* Mp = M + (size_t)o * 2304;
#pragma unroll
            for (int i = 0; i < 9; i++) wv9[i] = Mp[i * 256 + c];
#pragma unroll
            for (int k = 0; k < KK; k++) {
                const float* zp = Z + (size_t)k * NW + (size_t)o * 2304;
#pragma unroll
                for (int i = 0; i < 9; i++) wv9[i] += rvl[k] * zp[i * 256 + c];
            }
        }
#pragma unroll
        for (int i = 0; i < 9; i++) swv[i * 256 + c] = wv9[i];
        __syncthreads();

#pragma unroll
        for (int j = 0; j < 9; j++) {
            unsigned bit  = __float_as_uint(swv[c * 9 + j]) >> 31;
            unsigned mask = __ballot_sync(0xffffffffu, bit);
            if (lane == 0) {
                g_w[(o * 9 + j) * 8 + cw] = mask;
                atomicAdd(&sP[j], __popc(mask));
            }
        }
        __syncthreads();
        if (c < 9) g_corr[o * 9 + c] = 256 - 2 * sP[c];
        return;
    }

    const int gid = (blockIdx.x - COUT) * 256 + threadIdx.x;
    if (gid >= Bc * PPIX) return;
    const int b  = gid / PPIX;
    const int pp = gid - b * PPIX;
    const int py = pp / PDIM;
    const int px = pp - py * PDIM;

    uint4* dst = (uint4*)(g_pabits + ((size_t)b * PPIX + pp) * 8);

    if (py == 0 || py == PDIM - 1 || px == 0 || px == PDIM - 1) {
        uint4 z = make_uint4(0, 0, 0, 0);
        dst[0] = z; dst[1] = z;
        return;
    }
    const float* xp = x + (size_t)b * CIN * NPIX + (py - 1) * HW + (px - 1);
    uint32_t w[8];
#pragma unroll
    for (int cw = 0; cw < 8; cw++) {
        uint32_t m = 0;
#pragma unroll
        for (int j = 0; j < 32; j++) {
            uint32_t s = __float_as_uint(xp[(size_t)(cw * 32 + j) * NPIX]) >> 31;
            m |= s << j;
        }
        w[cw] = m;
    }
    dst[0] = make_uint4(w[0], w[1], w[2], w[3]);
    dst[1] = make_uint4(w[4], w[5], w[6], w[7]);
}

// ---------------------------------------------------------------------------
// Kernel 2: XNOR conv with carry-save compression (45 POPC/output vs 72).
// 4-row bands, 16 warps, half-row split (warps 0-7: x<14, 8-15: x>=14).
// grid <<<448, 512, 35456>>>
// ---------------------------------------------------------------------------
#define SM_ABITS 0                      // 6 rows x 30 px x 32B = 5760
#define SM_STAGE 5760                   // 8 outch-groups x 32 x 29 floats = 29696
#define SM_TOTAL (5760 + 29696)

__global__ void __launch_bounds__(512, 1)
conv_pop_kernel(const float* __restrict__ alpha, float* __restrict__ out)
{
    extern __shared__ __align__(16) uint8_t smem[];

    const int tid  = threadIdx.x;
    const int wid  = tid >> 5;
    const int lane = tid & 31;
    const int og   = wid & 7;           // outch group
    const int half = wid >> 3;          // 0: x 0..13, 1: x 14..27
    const int xs   = half * 14;

    const int b    = blockIdx.x / 7;
    const int band = blockIdx.x - b * 7;
    const int r0   = band * 4;

    // cooperative load: padded rows r0..r0+5 (360 uint4, contiguous)
    {
        const uint4* src = (const uint4*)(g_pabits + ((size_t)b * PPIX + r0 * PDIM) * 8);
        uint4* d4 = (uint4*)(smem + SM_ABITS);
        if (tid < 360) d4[tid] = src[tid];
    }

    const int o = og * 32 + lane;
    int corr[9];
#pragma unroll
    for (int t = 0; t < 9; t++) corr[t] = __ldg(g_corr + o * 9 + t);
    const float av = __ldg(alpha + o);

    // 72 weight words in registers
    uint32_t w[9][8];
    {
        const uint4* wp4 = (const uint4*)(g_w + o * 72);
#pragma unroll
        for (int t = 0; t < 9; t++) {
            uint4 q0 = __ldg(wp4 + t * 2), q1 = __ldg(wp4 + t * 2 + 1);
            w[t][0] = q0.x; w[t][1] = q0.y; w[t][2] = q0.z; w[t][3] = q0.w;
            w[t][4] = q1.x; w[t][5] = q1.y; w[t][6] = q1.z; w[t][7] = q1.w;
        }
    }

    __syncthreads();

    const uint32_t* ab = (const uint32_t*)(smem + SM_ABITS);
    float* stage = (float*)(smem + SM_STAGE) + og * (32 * 29);

#pragma unroll 1
    for (int ry = 0; ry < 4; ry++) {
        const int y = r0 + ry;

        const int rowc = (y == 0)  ? (corr[0] + corr[1] + corr[2])
                       : (y == 27) ? (corr[6] + corr[7] + corr[8]) : 0;
        int cedge = (half == 0) ? (corr[0] + corr[3] + corr[6])
                                : (corr[2] + corr[5] + corr[8]);
        if (y == 0)  cedge -= (half == 0) ? corr[0] : corr[2];
        if (y == 27) cedge -= (half == 0) ? corr[6] : corr[8];

#pragma unroll 1
        for (int i = 0; i < 14; i++) {
            int p1 = 0, p2 = 0;
#pragma unroll
            for (int kh = 0; kh < 3; kh++) {
                const uint32_t* rowp = ab + ((ry + kh) * PDIM + xs + i) * 8;
#pragma unroll
                for (int kw = 0; kw < 3; kw++) {
                    const uint4 a0 = *(const uint4*)(rowp + kw * 8);
                    const uint4 a1 = *(const uint4*)(rowp + kw * 8 + 4);
                    const int t = kh * 3 + kw;
                    const uint32_t x0 = a0.x ^ w[t][0], x1 = a0.y ^ w[t][1];
                    const uint32_t x2 = a0.z ^ w[t][2], x3 = a0.w ^ w[t][3];
                    const uint32_t x4 = a1.x ^ w[t][4], x5 = a1.y ^ w[t][5];
                    const uint32_t x6 = a1.z ^ w[t][6], x7 = a1.w ^ w[t][7];
                    // CSA: 8 words -> S (w1) + cA,cB,cC,C (w2)
                    const uint32_t sA = xor3(x0, x1, x2), cA = maj3(x0, x1, x2);
                    const uint32_t sB = xor3(x3, x4, x5), cB = maj3(x3, x4, x5);
                    const uint32_t sC = x6 ^ x7,          cC = x6 & x7;
                    const uint32_t S  = xor3(sA, sB, sC), C  = maj3(sA, sB, sC);
                    p1 += __popc(S);
                    p2 += __popc(cA) + __popc(cB) + __popc(cC) + __popc(C);
                }
                asm volatile("" ::: "memory");
            }
            const int mis = p1 + 2 * p2;
            int cs = rowc;
            if (half == 0 && i == 0)  cs += cedge;
            if (half == 1 && i == 13) cs += cedge;
            stage[lane * 29 + xs + i] = av * (float)(2304 - 2 * mis - cs);
        }

        __syncthreads();
        if (half == 1 && lane < HW) {
            float* outb = out + ((size_t)(b * COUT + og * 32) * HW + y) * HW;
#pragma unroll 4
            for (int oo = 0; oo < 32; oo++)
                outb[(size_t)oo * NPIX + lane] = stage[oo * 29 + lane];
        }
        __syncthreads();
    }
}

// ---------------------------------------------------------------------------
extern "C" void kernel_launch(void* const* d_in, const int* in_sizes, int n_in,
                              void* d_out, int out_size)
{
    const float* x  = (const float*)d_in[0];
    const float* M  = (const float*)d_in[1];
    const float* Z  = (const float*)d_in[2];
    const float* al = (const float*)d_in[3];
    const float* rv = (const float*)d_in[4];

    cudaFuncSetAttribute(conv_pop_kernel,
                         cudaFuncAttributeMaxDynamicSharedMemorySize, SM_TOTAL);

    prep_kernel<<<COUT + (Bc * PPIX + 255) / 256, 256>>>(M, Z, rv, x);
    conv_pop_kernel<<<Bc * 7, 512, SM_TOTAL>>>(al, (float*)d_out);
}